// round 13
// baseline (speedup 1.0000x reference)
#include <cuda_runtime.h>
#include <cuda_fp16.h>
#include <cstdint>
#include <math.h>

// Problem constants
#define BB 4
#define TT 2048
#define CC 1024
#define HH 16
#define DD 64
#define C3 3072          // 3*C
#define MTOT 8192        // B*T

// Scratch (device globals — no allocation in kernel_launch)
__device__ __half g_x16[(size_t)MTOT * CC];
__device__ __half g_wq16[(size_t)C3 * CC];
__device__ __half g_wo16[(size_t)CC * CC];
__device__ __half g_qkv16[(size_t)MTOT * C3];
__device__ __half g_at16[(size_t)MTOT * CC];

// ---------------------------------------------------------------------------
// Helpers
// ---------------------------------------------------------------------------
__device__ __forceinline__ unsigned sptr(const void* p) {
    return (unsigned)__cvta_generic_to_shared(p);
}

__device__ __forceinline__ void ldsm4(unsigned& r0, unsigned& r1,
                                      unsigned& r2, unsigned& r3, unsigned a) {
    asm volatile("ldmatrix.sync.aligned.m8n8.x4.shared.b16 {%0,%1,%2,%3}, [%4];"
                 : "=r"(r0), "=r"(r1), "=r"(r2), "=r"(r3) : "r"(a));
}

__device__ __forceinline__ void ldsm4t(unsigned& r0, unsigned& r1,
                                       unsigned& r2, unsigned& r3, unsigned a) {
    asm volatile("ldmatrix.sync.aligned.m8n8.x4.trans.shared.b16 {%0,%1,%2,%3}, [%4];"
                 : "=r"(r0), "=r"(r1), "=r"(r2), "=r"(r3) : "r"(a));
}

__device__ __forceinline__ void mma16816(float* c, const unsigned* a,
                                         unsigned b0, unsigned b1) {
    asm volatile(
        "mma.sync.aligned.m16n8k16.row.col.f32.f16.f16.f32 "
        "{%0,%1,%2,%3},{%4,%5,%6,%7},{%8,%9},{%0,%1,%2,%3};"
        : "+f"(c[0]), "+f"(c[1]), "+f"(c[2]), "+f"(c[3])
        : "r"(a[0]), "r"(a[1]), "r"(a[2]), "r"(a[3]), "r"(b0), "r"(b1));
}

__device__ __forceinline__ unsigned pack2(float x, float y) {
    __half2 h = __floats2half2_rn(x, y);
    return *(unsigned*)&h;
}

// exact *0.125 on packed fp16x2 (exponent shift)
__device__ __forceinline__ unsigned scale8(unsigned v) {
    __half2 t = *(__half2*)&v;
    t = __hmul2(t, __floats2half2_rn(0.125f, 0.125f));
    return *(unsigned*)&t;
}

// cp.async
__device__ __forceinline__ void cp16(unsigned saddr, const void* g) {
    asm volatile("cp.async.cg.shared.global [%0], [%1], 16;\n"
                 :: "r"(saddr), "l"(g));
}
template<int N> __device__ __forceinline__ void cp_wait() {
    asm volatile("cp.async.wait_group %0;\n" :: "n"(N) : "memory");
}
__device__ __forceinline__ void cp_commit() {
    asm volatile("cp.async.commit_group;\n" ::: "memory");
}

// ---------------------------------------------------------------------------
// Fused fp32 -> fp16 rounding of x, w_qkv, w_out in one launch.
// ---------------------------------------------------------------------------
__global__ __launch_bounds__(256) void round3_f16(
    const float* __restrict__ x,  __half* __restrict__ xo,  int nx,
    const float* __restrict__ w1, __half* __restrict__ w1o, int n1,
    const float* __restrict__ w2, __half* __restrict__ w2o, int n2)
{
    int base = (blockIdx.x * blockDim.x + threadIdx.x) * 4;
    const float* src;
    __half* dst;
    if (base < nx) {
        src = x + base; dst = xo + base;
    } else if (base < nx + n1) {
        src = w1 + (base - nx); dst = w1o + (base - nx);
    } else if (base < nx + n1 + n2) {
        src = w2 + (base - nx - n1); dst = w2o + (base - nx - n1);
    } else return;
    float4 v = *(const float4*)src;
    *(unsigned*)dst       = pack2(v.x, v.y);
    *(unsigned*)(dst + 2) = pack2(v.z, v.w);
}

// ---------------------------------------------------------------------------
// HMMA GEMM (NT), fp16: C = A*W^T (+bias).
// CTA tile 128x128, 4 warps (128 threads) in 2x2, warp tile 64x64, BK=64.
// 3-stage cp.async ring, ONE __syncthreads per K-slab (16 slabs): at iter c
// the load target (c+2)%3 == (c-1)%3, whose last reader finished at iter c-1
// and is protected by this iteration's sync. 2 CTAs/SM (221KB smem, 52k regs).
// ---------------------------------------------------------------------------
#define PADK 72           // 64 + 8 halves: 144B rows, conflict-free LDSM
#define STAGE_B 36864u    // 18432 (A 128x72) + 18432 (W 128x72)

__global__ __launch_bounds__(128) void gemm_f16(
    const __half* __restrict__ A, const __half* __restrict__ W,
    float* __restrict__ Cf, __half* __restrict__ Ch,
    const float* __restrict__ bias,
    int M, int N, int K)
{
    extern __shared__ __align__(16) __half sm[];

    const int tid  = threadIdx.x;
    const int lane = tid & 31;
    const int warp = tid >> 5;
    const int wm = (warp >> 1) * 64;
    const int wn = (warp & 1) * 64;
    const int brow = blockIdx.y * 128;
    const int bcol = blockIdx.x * 128;
    const int nch  = K >> 6;   // 16 slabs of 64

    const int tt  = lane >> 3;
    const int lr8 = lane & 7;
    const unsigned smb = sptr(sm);

    float acc[4][8][4];
#pragma unroll
    for (int mt = 0; mt < 4; mt++)
#pragma unroll
        for (int nt = 0; nt < 8; nt++)
#pragma unroll
            for (int i = 0; i < 4; i++) acc[mt][nt][i] = 0.0f;

    auto load_stage = [&](int c, int s) {
        const int k0 = c << 6;
        const unsigned sb = smb + (unsigned)s * STAGE_B;
#pragma unroll
        for (int i = 0; i < 8; i++) {          // A: 128 rows x 64 cols
            int idx = i * 128 + tid;
            int row = idx >> 3;
            int cc  = (idx & 7) * 8;
            cp16(sb + (unsigned)(row * PADK + cc) * 2,
                 A + (size_t)(brow + row) * K + k0 + cc);
        }
#pragma unroll
        for (int i = 0; i < 8; i++) {          // W: 128 rows x 64 cols
            int idx = i * 128 + tid;
            int row = idx >> 3;
            int cc  = (idx & 7) * 8;
            cp16(sb + 18432u + (unsigned)(row * PADK + cc) * 2,
                 W + (size_t)(bcol + row) * K + k0 + cc);
        }
        cp_commit();
    };

    load_stage(0, 0);
    load_stage(1, 1);

    for (int c = 0; c < nch; c++) {
        if (c + 2 <= nch - 1 + 1 && c + 2 <= nch) {
            // pending groups after preload/in-loop issue: 1 while more remain
        }
        if (c + 2 <= nch) cp_wait<1>();
        else              cp_wait<0>();
        __syncthreads();

        if (c + 2 < nch) load_stage(c + 2, (c + 2) % 3);

        const unsigned sb  = smb + (unsigned)(c % 3) * STAGE_B;
        const unsigned sbW = sb + 18432u;

#pragma unroll
        for (int ks = 0; ks < 64; ks += 16) {
            unsigned bw[8][2];
#pragma unroll
            for (int i = 0; i < 4; i++) {
                int nrow = wn + (2 * i + (tt >> 1)) * 8 + lr8;
                int ncol = ks + (tt & 1) * 8;
                ldsm4(bw[2 * i][0], bw[2 * i][1], bw[2 * i + 1][0], bw[2 * i + 1][1],
                      sbW + (unsigned)(nrow * PADK + ncol) * 2);
            }
#pragma unroll
            for (int mt = 0; mt < 4; mt++) {
                unsigned ah[4];
                int arow = wm + mt * 16 + (tt & 1) * 8 + lr8;
                int acol = ks + (tt >> 1) * 8;
                ldsm4(ah[0], ah[1], ah[2], ah[3],
                      sb + (unsigned)(arow * PADK + acol) * 2);
#pragma unroll
                for (int nt = 0; nt < 8; nt++)
                    mma16816(acc[mt][nt], ah, bw[nt][0], bw[nt][1]);
            }
        }
    }

    const int r  = lane >> 2;
    const int cq = lane & 3;
#pragma unroll
    for (int mt = 0; mt < 4; mt++) {
#pragma unroll
        for (int nt = 0; nt < 8; nt++) {
            int row0 = brow + wm + mt * 16 + r;
            int col0 = bcol + wn + nt * 8 + cq * 2;
            float b0 = 0.f, b1 = 0.f;
            if (bias != nullptr) { b0 = bias[col0]; b1 = bias[col0 + 1]; }
            float v0 = acc[mt][nt][0] + b0, v1 = acc[mt][nt][1] + b1;
            float v2 = acc[mt][nt][2] + b0, v3 = acc[mt][nt][3] + b1;
            if (Cf != nullptr) {
                *(float2*)(Cf + (size_t)row0 * N + col0)       = make_float2(v0, v1);
                *(float2*)(Cf + (size_t)(row0 + 8) * N + col0) = make_float2(v2, v3);
            }
            if (Ch != nullptr) {
                *(unsigned*)(Ch + (size_t)row0 * N + col0)       = pack2(v0, v1);
                *(unsigned*)(Ch + (size_t)(row0 + 8) * N + col0) = pack2(v2, v3);
            }
        }
    }
}

// ---------------------------------------------------------------------------
// Causal flash attention, fp16 (R12 version — at floor).
// Grid (16, 64). Br=128, Bc=64; 128 threads, 4 warps; warp w owns rows
// w*32..w*32+31 (two 16-row m-tiles). 4-stage cp.async ring, 1 sync/tile.
// ---------------------------------------------------------------------------
#define SKP 72                 // smem row stride in fp16 (conflict-free LDSM)
#define KV_HALF 9216u          // 64*72*2 bytes (one K or V buffer)
#define KV_STAGE 18432u        // K + V per stage

__global__ __launch_bounds__(128) void flash_attn_f16(
    const __half* __restrict__ qkv, __half* __restrict__ outp)
{
    extern __shared__ __align__(16) __half smA[];   // 4 stages x (K|V)

    const int tid  = threadIdx.x;
    const int lane = tid & 31;
    const int w    = tid >> 5;
    const int qt   = (gridDim.x - 1) - blockIdx.x;   // heavy tiles first
    const int bh   = blockIdx.y;
    const int b    = bh >> 4;
    const int h    = bh & 15;

    const int tt  = lane >> 3;
    const int lr8 = lane & 7;
    const int r   = lane >> 2;
    const int cq  = lane & 3;
    const unsigned smb = sptr(smA);

    // ---- stage Q (two 64-row halves through stage-0 K buffer) ----
    unsigned qa[2][4][4];
#pragma unroll
    for (int half = 0; half < 2; half++) {
        __syncthreads();
#pragma unroll
        for (int i = 0; i < 4; i++) {
            int idx = tid + i * 128;
            int row = idx >> 3;
            int c8  = (idx & 7) * 8;
            size_t g = (size_t)(b * TT + qt * 128 + half * 64 + row) * C3 + h * DD + c8;
            *(uint4*)(smA + row * SKP + c8) = *(const uint4*)(qkv + g);
        }
        __syncthreads();
        if ((w >> 1) == half) {
            int wq = (w & 1) * 32;
#pragma unroll
            for (int mq = 0; mq < 2; mq++) {
#pragma unroll
                for (int kc = 0; kc < 4; kc++) {
                    int qrow = wq + mq * 16 + (tt & 1) * 8 + lr8;
                    int qcol = kc * 16 + (tt >> 1) * 8;
                    ldsm4(qa[mq][kc][0], qa[mq][kc][1], qa[mq][kc][2], qa[mq][kc][3],
                          smb + (unsigned)(qrow * SKP + qcol) * 2);
#pragma unroll
                    for (int j = 0; j < 4; j++)
                        qa[mq][kc][j] = scale8(qa[mq][kc][j]);   // fold 1/sqrt(D)
                }
            }
        }
    }
    __syncthreads();   // Q frags extracted before K overwrites stage 0

    float o[2][8][4];
#pragma unroll
    for (int mq = 0; mq < 2; mq++)
#pragma unroll
        for (int nt = 0; nt < 8; nt++)
#pragma unroll
            for (int j = 0; j < 4; j++) o[mq][nt][j] = 0.0f;
    float mx[2][2] = {{-1e30f, -1e30f}, {-1e30f, -1e30f}};
    float li[2][2] = {{0.f, 0.f}, {0.f, 0.f}};

    const int nkt = 2 * qt + 2;

    // cp.async K/V tile loader: tile kt -> stage s
    auto load_tile = [&](int kt, int s) {
        const unsigned sb = smb + (unsigned)s * KV_STAGE;
        size_t base = (size_t)(b * TT + kt * 64) * C3 + h * DD;
#pragma unroll
        for (int i = 0; i < 4; i++) {
            int idx = tid + i * 128;
            int row = idx >> 3;
            int c8  = (idx & 7) * 8;
            unsigned d = sb + (unsigned)(row * SKP + c8) * 2;
            size_t g = base + (size_t)row * C3 + c8;
            cp16(d,           qkv + g + CC);       // K
            cp16(d + KV_HALF, qkv + g + 2 * CC);   // V
        }
        cp_commit();
    };

    load_tile(0, 0);
    if (nkt > 1) load_tile(1, 1);
    if (nkt > 2) load_tile(2, 2);

    for (int kt = 0; kt < nkt; kt++) {
        int rem = nkt - 1 - kt;
        if (rem >= 2)      cp_wait<2>();
        else if (rem == 1) cp_wait<1>();
        else               cp_wait<0>();
        __syncthreads();

        if (kt + 3 < nkt) load_tile(kt + 3, (kt + 3) & 3);

        const unsigned sbK = smb + (unsigned)(kt & 3) * KV_STAGE;
        const unsigned sbV = sbK + KV_HALF;

        if (kt * 64 <= qt * 128 + w * 32 + 31) {
            // ---- scores: S = Q·K^T (both m-tiles share K frags) ----
            float s[2][8][4];
#pragma unroll
            for (int mq = 0; mq < 2; mq++)
#pragma unroll
                for (int nt = 0; nt < 8; nt++)
#pragma unroll
                    for (int j = 0; j < 4; j++) s[mq][nt][j] = 0.0f;

#pragma unroll
            for (int kc = 0; kc < 4; kc++) {
                unsigned kb[8][2];
#pragma unroll
                for (int i = 0; i < 4; i++) {
                    int nrow = (2 * i + (tt >> 1)) * 8 + lr8;
                    int ncol = kc * 16 + (tt & 1) * 8;
                    ldsm4(kb[2 * i][0], kb[2 * i][1], kb[2 * i + 1][0], kb[2 * i + 1][1],
                          sbK + (unsigned)(nrow * SKP + ncol) * 2);
                }
#pragma unroll
                for (int mq = 0; mq < 2; mq++)
#pragma unroll
                    for (int nt = 0; nt < 8; nt++)
                        mma16816(s[mq][nt], qa[mq][kc], kb[nt][0], kb[nt][1]);
            }

            // ---- causal mask (diagonal-crossing tiles only) ----
            if (kt >= 2 * qt) {
                int colb = kt * 64 + cq * 2;
#pragma unroll
                for (int mq = 0; mq < 2; mq++) {
                    int rowr  = qt * 128 + w * 32 + mq * 16 + r;
                    int rowr8 = rowr + 8;
#pragma unroll
                    for (int nt = 0; nt < 8; nt++) {
                        int c0 = colb + nt * 8;
                        if (c0 > rowr)      s[mq][nt][0] = -1e30f;
                        if (c0 + 1 > rowr)  s[mq][nt][1] = -1e30f;
                        if (c0 > rowr8)     s[mq][nt][2] = -1e30f;
                        if (c0 + 1 > rowr8) s[mq][nt][3] = -1e30f;
                    }
                }
            }

            // ---- online softmax per m-tile ----
#pragma unroll
            for (int mq = 0; mq < 2; mq++) {
                float mr = -1e30f, mr8 = -1e30f;
#pragma unroll
                for (int nt = 0; nt < 8; nt++) {
                    mr  = fmaxf(mr,  fmaxf(s[mq][nt][0], s[mq][nt][1]));
                    mr8 = fmaxf(mr8, fmaxf(s[mq][nt][2], s[mq][nt][3]));
                }
                mr  = fmaxf(mr,  __shfl_xor_sync(0xffffffffu, mr, 1));
                mr  = fmaxf(mr,  __shfl_xor_sync(0xffffffffu, mr, 2));
                mr8 = fmaxf(mr8, __shfl_xor_sync(0xffffffffu, mr8, 1));
                mr8 = fmaxf(mr8, __shfl_xor_sync(0xffffffffu, mr8, 2));

                float mn  = fmaxf(mx[mq][0], mr);
                float mn8 = fmaxf(mx[mq][1], mr8);
                float ar  = __expf(mx[mq][0] - mn);
                float ar8 = __expf(mx[mq][1] - mn8);
                mx[mq][0] = mn; mx[mq][1] = mn8;

                float lsr = 0.f, lsr8 = 0.f;
#pragma unroll
                for (int nt = 0; nt < 8; nt++) {
                    float p0 = __expf(s[mq][nt][0] - mn);
                    float p1 = __expf(s[mq][nt][1] - mn);
                    float p2 = __expf(s[mq][nt][2] - mn8);
                    float p3 = __expf(s[mq][nt][3] - mn8);
                    lsr += p0 + p1; lsr8 += p2 + p3;
                    s[mq][nt][0] = p0; s[mq][nt][1] = p1;
                    s[mq][nt][2] = p2; s[mq][nt][3] = p3;
                    o[mq][nt][0] *= ar;  o[mq][nt][1] *= ar;
                    o[mq][nt][2] *= ar8; o[mq][nt][3] *= ar8;
                }
                li[mq][0] = li[mq][0] * ar  + lsr;
                li[mq][1] = li[mq][1] * ar8 + lsr8;
            }

            // ---- PV: O += P·V (both m-tiles share V frags) ----
#pragma unroll
            for (int kc = 0; kc < 4; kc++) {
                unsigned pa[2][4];
#pragma unroll
                for (int mq = 0; mq < 2; mq++) {
                    pa[mq][0] = pack2(s[mq][2 * kc][0],     s[mq][2 * kc][1]);
                    pa[mq][1] = pack2(s[mq][2 * kc][2],     s[mq][2 * kc][3]);
                    pa[mq][2] = pack2(s[mq][2 * kc + 1][0], s[mq][2 * kc + 1][1]);
                    pa[mq][3] = pack2(s[mq][2 * kc + 1][2], s[mq][2 * kc + 1][3]);
                }
                unsigned vb[8][2];
#pragma unroll
                for (int i = 0; i < 4; i++) {
                    int vrow = kc * 16 + (tt & 1) * 8 + lr8;
                    int vcol = (2 * i + (tt >> 1)) * 8;
                    ldsm4t(vb[2 * i][0], vb[2 * i][1], vb[2 * i + 1][0], vb[2 * i + 1][1],
                           sbV + (unsigned)(vrow * SKP + vcol) * 2);
                }
#pragma unroll
                for (int mq = 0; mq < 2; mq++)
#pragma unroll
                    for (int nt = 0; nt < 8; nt++)
                        mma16816(o[mq][nt], pa[mq], vb[nt][0], vb[nt][1]);
            }
        }
    }

    // ---- finalize ----
#pragma unroll
    for (int mq = 0; mq < 2; mq++) {
        float l0 = li[mq][0], l8 = li[mq][1];
        l0 += __shfl_xor_sync(0xffffffffu, l0, 1);
        l0 += __shfl_xor_sync(0xffffffffu, l0, 2);
        l8 += __shfl_xor_sync(0xffffffffu, l8, 1);
        l8 += __shfl_xor_sync(0xffffffffu, l8, 2);
        float inv  = 1.0f / l0;
        float inv8 = 1.0f / l8;
        int rowr  = qt * 128 + w * 32 + mq * 16 + r;
        int rowr8 = rowr + 8;
#pragma unroll
        for (int nt = 0; nt < 8; nt++) {
            size_t a0 = (size_t)(b * TT + rowr)  * CC + h * DD + nt * 8 + cq * 2;
            size_t a1 = (size_t)(b * TT + rowr8) * CC + h * DD + nt * 8 + cq * 2;
            *(unsigned*)(outp + a0) = pack2(o[mq][nt][0] * inv,  o[mq][nt][1] * inv);
            *(unsigned*)(outp + a1) = pack2(o[mq][nt][2] * inv8, o[mq][nt][3] * inv8);
        }
    }
}

// ---------------------------------------------------------------------------
extern "C" void kernel_launch(void* const* d_in, const int* in_sizes, int n_in,
                              void* d_out, int out_size)
{
    const float* x     = (const float*)d_in[0];
    const float* w_qkv = (const float*)d_in[1];
    const float* w_out = (const float*)d_in[2];
    const float* b_out = (const float*)d_in[3];
    float* out = (float*)d_out;

    __half *x16, *wq16, *wo16, *qkv16, *at16;
    cudaGetSymbolAddress((void**)&x16,   g_x16);
    cudaGetSymbolAddress((void**)&wq16,  g_wq16);
    cudaGetSymbolAddress((void**)&wo16,  g_wo16);
    cudaGetSymbolAddress((void**)&qkv16, g_qkv16);
    cudaGetSymbolAddress((void**)&at16,  g_at16);

    const int dsmemG = 3 * (int)STAGE_B;   // 110.6KB GEMM ring (2 CTAs/SM)
    const int dsmemA = 4 * (int)KV_STAGE;  // 72KB attention ring
    cudaFuncSetAttribute(gemm_f16, cudaFuncAttributeMaxDynamicSharedMemorySize, dsmemG);
    cudaFuncSetAttribute(flash_attn_f16, cudaFuncAttributeMaxDynamicSharedMemorySize, dsmemA);

    // 0) round inputs to fp16 (single fused launch)
    {
        int nx = MTOT * CC;
        int n1 = C3 * CC;
        int n2 = CC * CC;
        int total4 = (nx + n1 + n2) / 4;
        round3_f16<<<(total4 + 255) / 256, 256>>>(x, x16, nx, w_qkv, wq16, n1,
                                                  w_out, wo16, n2);
    }

    // 1) QKV projection -> fp16
    {
        dim3 grid(C3 / 128, MTOT / 128);
        gemm_f16<<<grid, 128, dsmemG>>>(x16, wq16, nullptr, qkv16, nullptr, MTOT, C3, CC);
    }

    // 2) causal flash attention -> fp16
    {
        dim3 grid(TT / 128, BB * HH);
        flash_attn_f16<<<grid, 128, dsmemA>>>(qkv16, at16);
    }

    // 3) out projection + bias -> fp32 output
    {
        dim3 grid(CC / 128, MTOT / 128);
        gemm_f16<<<grid, 128, dsmemG>>>(at16, wo16, out, nullptr, b_out, MTOT, CC, CC);
    }
}

// round 14
// speedup vs baseline: 1.0373x; 1.0373x over previous
#include <cuda_runtime.h>
#include <cuda_fp16.h>
#include <cstdint>
#include <math.h>

// Problem constants
#define BB 4
#define TT 2048
#define CC 1024
#define HH 16
#define DD 64
#define C3 3072          // 3*C
#define MTOT 8192        // B*T

// Scratch (device globals — no allocation in kernel_launch)
__device__ __half g_x16[(size_t)MTOT * CC];
__device__ __half g_wq16[(size_t)C3 * CC];
__device__ __half g_wo16[(size_t)CC * CC];
__device__ __half g_qkv16[(size_t)MTOT * C3];
__device__ __half g_at16[(size_t)MTOT * CC];

// ---------------------------------------------------------------------------
// Helpers
// ---------------------------------------------------------------------------
__device__ __forceinline__ unsigned sptr(const void* p) {
    return (unsigned)__cvta_generic_to_shared(p);
}

__device__ __forceinline__ void ldsm4(unsigned& r0, unsigned& r1,
                                      unsigned& r2, unsigned& r3, unsigned a) {
    asm volatile("ldmatrix.sync.aligned.m8n8.x4.shared.b16 {%0,%1,%2,%3}, [%4];"
                 : "=r"(r0), "=r"(r1), "=r"(r2), "=r"(r3) : "r"(a));
}

__device__ __forceinline__ void ldsm4t(unsigned& r0, unsigned& r1,
                                       unsigned& r2, unsigned& r3, unsigned a) {
    asm volatile("ldmatrix.sync.aligned.m8n8.x4.trans.shared.b16 {%0,%1,%2,%3}, [%4];"
                 : "=r"(r0), "=r"(r1), "=r"(r2), "=r"(r3) : "r"(a));
}

__device__ __forceinline__ void mma16816(float* c, const unsigned* a,
                                         unsigned b0, unsigned b1) {
    asm volatile(
        "mma.sync.aligned.m16n8k16.row.col.f32.f16.f16.f32 "
        "{%0,%1,%2,%3},{%4,%5,%6,%7},{%8,%9},{%0,%1,%2,%3};"
        : "+f"(c[0]), "+f"(c[1]), "+f"(c[2]), "+f"(c[3])
        : "r"(a[0]), "r"(a[1]), "r"(a[2]), "r"(a[3]), "r"(b0), "r"(b1));
}

__device__ __forceinline__ unsigned pack2(float x, float y) {
    __half2 h = __floats2half2_rn(x, y);
    return *(unsigned*)&h;
}

// exact *0.125 on packed fp16x2 (exponent shift)
__device__ __forceinline__ unsigned scale8(unsigned v) {
    __half2 t = *(__half2*)&v;
    t = __hmul2(t, __floats2half2_rn(0.125f, 0.125f));
    return *(unsigned*)&t;
}

// cp.async
__device__ __forceinline__ void cp16(unsigned saddr, const void* g) {
    asm volatile("cp.async.cg.shared.global [%0], [%1], 16;\n"
                 :: "r"(saddr), "l"(g));
}
template<int N> __device__ __forceinline__ void cp_wait() {
    asm volatile("cp.async.wait_group %0;\n" :: "n"(N) : "memory");
}
__device__ __forceinline__ void cp_commit() {
    asm volatile("cp.async.commit_group;\n" ::: "memory");
}

// ---------------------------------------------------------------------------
// Fused fp32 -> fp16 rounding of x, w_qkv, w_out in one launch.
// All sizes are multiples of 4.
// ---------------------------------------------------------------------------
__global__ __launch_bounds__(256) void round3_f16(
    const float* __restrict__ x,  __half* __restrict__ xo,  int nx,
    const float* __restrict__ w1, __half* __restrict__ w1o, int n1,
    const float* __restrict__ w2, __half* __restrict__ w2o, int n2)
{
    int base = (blockIdx.x * blockDim.x + threadIdx.x) * 4;
    const float* src;
    __half* dst;
    if (base < nx) {
        src = x + base; dst = xo + base;
    } else if (base < nx + n1) {
        src = w1 + (base - nx); dst = w1o + (base - nx);
    } else if (base < nx + n1 + n2) {
        src = w2 + (base - nx - n1); dst = w2o + (base - nx - n1);
    } else return;
    float4 v = *(const float4*)src;
    *(unsigned*)dst       = pack2(v.x, v.y);
    *(unsigned*)(dst + 2) = pack2(v.z, v.w);
}

// ---------------------------------------------------------------------------
// HMMA GEMM (NT), fp16: C = A*W^T (+bias).  (R12 configuration — best known.)
// CTA tile 128x128, 4 warps (128 threads) in 2x2, warp tile 64x64, BK=32.
// 4-stage cp.async ring, ONE __syncthreads per K-slab: at iter c the load
// target (c+3)&3 == (c-1)&3, whose last reader finished before this sync.
// 2 CTAs/SM (160KB smem, 52k regs).
// ---------------------------------------------------------------------------
#define PADK 40
#define STAGE_B 20480u    // 10240 (A 128x40) + 10240 (W 128x40)

__global__ __launch_bounds__(128) void gemm_f16(
    const __half* __restrict__ A, const __half* __restrict__ W,
    float* __restrict__ Cf, __half* __restrict__ Ch,
    const float* __restrict__ bias,
    int M, int N, int K)
{
    extern __shared__ __align__(16) __half sm[];

    const int tid  = threadIdx.x;
    const int lane = tid & 31;
    const int warp = tid >> 5;
    const int wm = (warp >> 1) * 64;
    const int wn = (warp & 1) * 64;
    const int brow = blockIdx.y * 128;
    const int bcol = blockIdx.x * 128;
    const int nch  = K >> 5;   // 32

    const int tt  = lane >> 3;
    const int lr8 = lane & 7;
    const unsigned smb = sptr(sm);

    float acc[4][8][4];
#pragma unroll
    for (int mt = 0; mt < 4; mt++)
#pragma unroll
        for (int nt = 0; nt < 8; nt++)
#pragma unroll
            for (int i = 0; i < 4; i++) acc[mt][nt][i] = 0.0f;

    auto load_stage = [&](int c, int s) {
        const int k0 = c << 5;
        const unsigned sb = smb + (unsigned)s * STAGE_B;
#pragma unroll
        for (int i = 0; i < 4; i++) {          // A: 128 rows x 32 cols
            int idx = i * 128 + tid;
            int row = idx >> 2;
            int cc  = (idx & 3) * 8;
            cp16(sb + (unsigned)(row * PADK + cc) * 2,
                 A + (size_t)(brow + row) * K + k0 + cc);
        }
#pragma unroll
        for (int i = 0; i < 4; i++) {          // W: 128 rows x 32 cols
            int idx = i * 128 + tid;
            int row = idx >> 2;
            int cc  = (idx & 3) * 8;
            cp16(sb + 10240u + (unsigned)(row * PADK + cc) * 2,
                 W + (size_t)(bcol + row) * K + k0 + cc);
        }
        cp_commit();
    };

    load_stage(0, 0);
    load_stage(1, 1);
    load_stage(2, 2);

    for (int c = 0; c < nch; c++) {
        int rem = nch - 1 - c;
        if (rem >= 2)      cp_wait<2>();
        else if (rem == 1) cp_wait<1>();
        else               cp_wait<0>();
        __syncthreads();

        if (c + 3 < nch) load_stage(c + 3, (c + 3) & 3);

        const unsigned sb  = smb + (unsigned)(c & 3) * STAGE_B;
        const unsigned sbW = sb + 10240u;

#pragma unroll
        for (int ks = 0; ks < 32; ks += 16) {
            unsigned bw[8][2];
#pragma unroll
            for (int i = 0; i < 4; i++) {
                int nrow = wn + (2 * i + (tt >> 1)) * 8 + lr8;
                int ncol = ks + (tt & 1) * 8;
                ldsm4(bw[2 * i][0], bw[2 * i][1], bw[2 * i + 1][0], bw[2 * i + 1][1],
                      sbW + (unsigned)(nrow * PADK + ncol) * 2);
            }
#pragma unroll
            for (int mt = 0; mt < 4; mt++) {
                unsigned ah[4];
                int arow = wm + mt * 16 + (tt & 1) * 8 + lr8;
                int acol = ks + (tt >> 1) * 8;
                ldsm4(ah[0], ah[1], ah[2], ah[3],
                      sb + (unsigned)(arow * PADK + acol) * 2);
#pragma unroll
                for (int nt = 0; nt < 8; nt++)
                    mma16816(acc[mt][nt], ah, bw[nt][0], bw[nt][1]);
            }
        }
    }

    const int r  = lane >> 2;
    const int cq = lane & 3;
#pragma unroll
    for (int mt = 0; mt < 4; mt++) {
#pragma unroll
        for (int nt = 0; nt < 8; nt++) {
            int row0 = brow + wm + mt * 16 + r;
            int col0 = bcol + wn + nt * 8 + cq * 2;
            float b0 = 0.f, b1 = 0.f;
            if (bias != nullptr) { b0 = bias[col0]; b1 = bias[col0 + 1]; }
            float v0 = acc[mt][nt][0] + b0, v1 = acc[mt][nt][1] + b1;
            float v2 = acc[mt][nt][2] + b0, v3 = acc[mt][nt][3] + b1;
            if (Cf != nullptr) {
                *(float2*)(Cf + (size_t)row0 * N + col0)       = make_float2(v0, v1);
                *(float2*)(Cf + (size_t)(row0 + 8) * N + col0) = make_float2(v2, v3);
            }
            if (Ch != nullptr) {
                *(unsigned*)(Ch + (size_t)row0 * N + col0)       = pack2(v0, v1);
                *(unsigned*)(Ch + (size_t)(row0 + 8) * N + col0) = pack2(v2, v3);
            }
        }
    }
}

// ---------------------------------------------------------------------------
// Causal flash attention, fp16 (R12 version — at floor).
// Grid (16, 64). Br=128, Bc=64; 128 threads, 4 warps; warp w owns rows
// w*32..w*32+31 (two 16-row m-tiles). 4-stage cp.async ring, 1 sync/tile.
// ---------------------------------------------------------------------------
#define SKP 72                 // smem row stride in fp16 (conflict-free LDSM)
#define KV_HALF 9216u          // 64*72*2 bytes (one K or V buffer)
#define KV_STAGE 18432u        // K + V per stage

__global__ __launch_bounds__(128) void flash_attn_f16(
    const __half* __restrict__ qkv, __half* __restrict__ outp)
{
    extern __shared__ __align__(16) __half smA[];   // 4 stages x (K|V)

    const int tid  = threadIdx.x;
    const int lane = tid & 31;
    const int w    = tid >> 5;
    const int qt   = (gridDim.x - 1) - blockIdx.x;   // heavy tiles first
    const int bh   = blockIdx.y;
    const int b    = bh >> 4;
    const int h    = bh & 15;

    const int tt  = lane >> 3;
    const int lr8 = lane & 7;
    const int r   = lane >> 2;
    const int cq  = lane & 3;
    const unsigned smb = sptr(smA);

    // ---- stage Q (two 64-row halves through stage-0 K buffer) ----
    unsigned qa[2][4][4];
#pragma unroll
    for (int half = 0; half < 2; half++) {
        __syncthreads();
#pragma unroll
        for (int i = 0; i < 4; i++) {
            int idx = tid + i * 128;
            int row = idx >> 3;
            int c8  = (idx & 7) * 8;
            size_t g = (size_t)(b * TT + qt * 128 + half * 64 + row) * C3 + h * DD + c8;
            *(uint4*)(smA + row * SKP + c8) = *(const uint4*)(qkv + g);
        }
        __syncthreads();
        if ((w >> 1) == half) {
            int wq = (w & 1) * 32;
#pragma unroll
            for (int mq = 0; mq < 2; mq++) {
#pragma unroll
                for (int kc = 0; kc < 4; kc++) {
                    int qrow = wq + mq * 16 + (tt & 1) * 8 + lr8;
                    int qcol = kc * 16 + (tt >> 1) * 8;
                    ldsm4(qa[mq][kc][0], qa[mq][kc][1], qa[mq][kc][2], qa[mq][kc][3],
                          smb + (unsigned)(qrow * SKP + qcol) * 2);
#pragma unroll
                    for (int j = 0; j < 4; j++)
                        qa[mq][kc][j] = scale8(qa[mq][kc][j]);   // fold 1/sqrt(D)
                }
            }
        }
    }
    __syncthreads();   // Q frags extracted before K overwrites stage 0

    float o[2][8][4];
#pragma unroll
    for (int mq = 0; mq < 2; mq++)
#pragma unroll
        for (int nt = 0; nt < 8; nt++)
#pragma unroll
            for (int j = 0; j < 4; j++) o[mq][nt][j] = 0.0f;
    float mx[2][2] = {{-1e30f, -1e30f}, {-1e30f, -1e30f}};
    float li[2][2] = {{0.f, 0.f}, {0.f, 0.f}};

    const int nkt = 2 * qt + 2;

    // cp.async K/V tile loader: tile kt -> stage s
    auto load_tile = [&](int kt, int s) {
        const unsigned sb = smb + (unsigned)s * KV_STAGE;
        size_t base = (size_t)(b * TT + kt * 64) * C3 + h * DD;
#pragma unroll
        for (int i = 0; i < 4; i++) {
            int idx = tid + i * 128;
            int row = idx >> 3;
            int c8  = (idx & 7) * 8;
            unsigned d = sb + (unsigned)(row * SKP + c8) * 2;
            size_t g = base + (size_t)row * C3 + c8;
            cp16(d,           qkv + g + CC);       // K
            cp16(d + KV_HALF, qkv + g + 2 * CC);   // V
        }
        cp_commit();
    };

    load_tile(0, 0);
    if (nkt > 1) load_tile(1, 1);
    if (nkt > 2) load_tile(2, 2);

    for (int kt = 0; kt < nkt; kt++) {
        int rem = nkt - 1 - kt;
        if (rem >= 2)      cp_wait<2>();
        else if (rem == 1) cp_wait<1>();
        else               cp_wait<0>();
        __syncthreads();

        if (kt + 3 < nkt) load_tile(kt + 3, (kt + 3) & 3);

        const unsigned sbK = smb + (unsigned)(kt & 3) * KV_STAGE;
        const unsigned sbV = sbK + KV_HALF;

        if (kt * 64 <= qt * 128 + w * 32 + 31) {
            // ---- scores: S = Q·K^T (both m-tiles share K frags) ----
            float s[2][8][4];
#pragma unroll
            for (int mq = 0; mq < 2; mq++)
#pragma unroll
                for (int nt = 0; nt < 8; nt++)
#pragma unroll
                    for (int j = 0; j < 4; j++) s[mq][nt][j] = 0.0f;

#pragma unroll
            for (int kc = 0; kc < 4; kc++) {
                unsigned kb[8][2];
#pragma unroll
                for (int i = 0; i < 4; i++) {
                    int nrow = (2 * i + (tt >> 1)) * 8 + lr8;
                    int ncol = kc * 16 + (tt & 1) * 8;
                    ldsm4(kb[2 * i][0], kb[2 * i][1], kb[2 * i + 1][0], kb[2 * i + 1][1],
                          sbK + (unsigned)(nrow * SKP + ncol) * 2);
                }
#pragma unroll
                for (int mq = 0; mq < 2; mq++)
#pragma unroll
                    for (int nt = 0; nt < 8; nt++)
                        mma16816(s[mq][nt], qa[mq][kc], kb[nt][0], kb[nt][1]);
            }

            // ---- causal mask (diagonal-crossing tiles only) ----
            if (kt >= 2 * qt) {
                int colb = kt * 64 + cq * 2;
#pragma unroll
                for (int mq = 0; mq < 2; mq++) {
                    int rowr  = qt * 128 + w * 32 + mq * 16 + r;
                    int rowr8 = rowr + 8;
#pragma unroll
                    for (int nt = 0; nt < 8; nt++) {
                        int c0 = colb + nt * 8;
                        if (c0 > rowr)      s[mq][nt][0] = -1e30f;
                        if (c0 + 1 > rowr)  s[mq][nt][1] = -1e30f;
                        if (c0 > rowr8)     s[mq][nt][2] = -1e30f;
                        if (c0 + 1 > rowr8) s[mq][nt][3] = -1e30f;
                    }
                }
            }

            // ---- online softmax per m-tile ----
#pragma unroll
            for (int mq = 0; mq < 2; mq++) {
                float mr = -1e30f, mr8 = -1e30f;
#pragma unroll
                for (int nt = 0; nt < 8; nt++) {
                    mr  = fmaxf(mr,  fmaxf(s[mq][nt][0], s[mq][nt][1]));
                    mr8 = fmaxf(mr8, fmaxf(s[mq][nt][2], s[mq][nt][3]));
                }
                mr  = fmaxf(mr,  __shfl_xor_sync(0xffffffffu, mr, 1));
                mr  = fmaxf(mr,  __shfl_xor_sync(0xffffffffu, mr, 2));
                mr8 = fmaxf(mr8, __shfl_xor_sync(0xffffffffu, mr8, 1));
                mr8 = fmaxf(mr8, __shfl_xor_sync(0xffffffffu, mr8, 2));

                float mn  = fmaxf(mx[mq][0], mr);
                float mn8 = fmaxf(mx[mq][1], mr8);
                float ar  = __expf(mx[mq][0] - mn);
                float ar8 = __expf(mx[mq][1] - mn8);
                mx[mq][0] = mn; mx[mq][1] = mn8;

                float lsr = 0.f, lsr8 = 0.f;
#pragma unroll
                for (int nt = 0; nt < 8; nt++) {
                    float p0 = __expf(s[mq][nt][0] - mn);
                    float p1 = __expf(s[mq][nt][1] - mn);
                    float p2 = __expf(s[mq][nt][2] - mn8);
                    float p3 = __expf(s[mq][nt][3] - mn8);
                    lsr += p0 + p1; lsr8 += p2 + p3;
                    s[mq][nt][0] = p0; s[mq][nt][1] = p1;
                    s[mq][nt][2] = p2; s[mq][nt][3] = p3;
                    o[mq][nt][0] *= ar;  o[mq][nt][1] *= ar;
                    o[mq][nt][2] *= ar8; o[mq][nt][3] *= ar8;
                }
                li[mq][0] = li[mq][0] * ar  + lsr;
                li[mq][1] = li[mq][1] * ar8 + lsr8;
            }

            // ---- PV: O += P·V (both m-tiles share V frags) ----
#pragma unroll
            for (int kc = 0; kc < 4; kc++) {
                unsigned pa[2][4];
#pragma unroll
                for (int mq = 0; mq < 2; mq++) {
                    pa[mq][0] = pack2(s[mq][2 * kc][0],     s[mq][2 * kc][1]);
                    pa[mq][1] = pack2(s[mq][2 * kc][2],     s[mq][2 * kc][3]);
                    pa[mq][2] = pack2(s[mq][2 * kc + 1][0], s[mq][2 * kc + 1][1]);
                    pa[mq][3] = pack2(s[mq][2 * kc + 1][2], s[mq][2 * kc + 1][3]);
                }
                unsigned vb[8][2];
#pragma unroll
                for (int i = 0; i < 4; i++) {
                    int vrow = kc * 16 + (tt & 1) * 8 + lr8;
                    int vcol = (2 * i + (tt >> 1)) * 8;
                    ldsm4t(vb[2 * i][0], vb[2 * i][1], vb[2 * i + 1][0], vb[2 * i + 1][1],
                           sbV + (unsigned)(vrow * SKP + vcol) * 2);
                }
#pragma unroll
                for (int mq = 0; mq < 2; mq++)
#pragma unroll
                    for (int nt = 0; nt < 8; nt++)
                        mma16816(o[mq][nt], pa[mq], vb[nt][0], vb[nt][1]);
            }
        }
    }

    // ---- finalize ----
#pragma unroll
    for (int mq = 0; mq < 2; mq++) {
        float l0 = li[mq][0], l8 = li[mq][1];
        l0 += __shfl_xor_sync(0xffffffffu, l0, 1);
        l0 += __shfl_xor_sync(0xffffffffu, l0, 2);
        l8 += __shfl_xor_sync(0xffffffffu, l8, 1);
        l8 += __shfl_xor_sync(0xffffffffu, l8, 2);
        float inv  = 1.0f / l0;
        float inv8 = 1.0f / l8;
        int rowr  = qt * 128 + w * 32 + mq * 16 + r;
        int rowr8 = rowr + 8;
#pragma unroll
        for (int nt = 0; nt < 8; nt++) {
            size_t a0 = (size_t)(b * TT + rowr)  * CC + h * DD + nt * 8 + cq * 2;
            size_t a1 = (size_t)(b * TT + rowr8) * CC + h * DD + nt * 8 + cq * 2;
            *(unsigned*)(outp + a0) = pack2(o[mq][nt][0] * inv,  o[mq][nt][1] * inv);
            *(unsigned*)(outp + a1) = pack2(o[mq][nt][2] * inv8, o[mq][nt][3] * inv8);
        }
    }
}

// ---------------------------------------------------------------------------
extern "C" void kernel_launch(void* const* d_in, const int* in_sizes, int n_in,
                              void* d_out, int out_size)
{
    const float* x     = (const float*)d_in[0];
    const float* w_qkv = (const float*)d_in[1];
    const float* w_out = (const float*)d_in[2];
    const float* b_out = (const float*)d_in[3];
    float* out = (float*)d_out;

    __half *x16, *wq16, *wo16, *qkv16, *at16;
    cudaGetSymbolAddress((void**)&x16,   g_x16);
    cudaGetSymbolAddress((void**)&wq16,  g_wq16);
    cudaGetSymbolAddress((void**)&wo16,  g_wo16);
    cudaGetSymbolAddress((void**)&qkv16, g_qkv16);
    cudaGetSymbolAddress((void**)&at16,  g_at16);

    const int dsmemG = 4 * (int)STAGE_B;   // 80KB GEMM ring
    const int dsmemA = 4 * (int)KV_STAGE;  // 72KB attention ring
    cudaFuncSetAttribute(gemm_f16, cudaFuncAttributeMaxDynamicSharedMemorySize, dsmemG);
    cudaFuncSetAttribute(flash_attn_f16, cudaFuncAttributeMaxDynamicSharedMemorySize, dsmemA);

    // 0) round inputs to fp16 (single fused launch)
    {
        int nx = MTOT * CC;
        int n1 = C3 * CC;
        int n2 = CC * CC;
        int total4 = (nx + n1 + n2) / 4;
        round3_f16<<<(total4 + 255) / 256, 256>>>(x, x16, nx, w_qkv, wq16, n1,
                                                  w_out, wo16, n2);
    }

    // 1) QKV projection -> fp16
    {
        dim3 grid(C3 / 128, MTOT / 128);
        gemm_f16<<<grid, 128, dsmemG>>>(x16, wq16, nullptr, qkv16, nullptr, MTOT, C3, CC);
    }

    // 2) causal flash attention -> fp16
    {
        dim3 grid(TT / 128, BB * HH);
        flash_attn_f16<<<grid, 128, dsmemA>>>(qkv16, at16);
    }

    // 3) out projection + bias -> fp32 output
    {
        dim3 grid(CC / 128, MTOT / 128);
        gemm_f16<<<grid, 128, dsmemG>>>(at16, wo16, out, nullptr, b_out, MTOT, CC, CC);
    }
}

// round 15
// speedup vs baseline: 1.0402x; 1.0028x over previous
#include <cuda_runtime.h>
#include <cuda_fp16.h>
#include <cstdint>
#include <math.h>

// Problem constants
#define BB 4
#define TT 2048
#define CC 1024
#define HH 16
#define DD 64
#define C3 3072          // 3*C
#define MTOT 8192        // B*T

// Scratch (device globals — no allocation in kernel_launch)
__device__ __half g_x16[(size_t)MTOT * CC];
__device__ __half g_wq16[(size_t)C3 * CC];
__device__ __half g_wo16[(size_t)CC * CC];
__device__ __half g_qkv16[(size_t)MTOT * C3];
__device__ __half g_at16[(size_t)MTOT * CC];

// ---------------------------------------------------------------------------
// Helpers
// ---------------------------------------------------------------------------
__device__ __forceinline__ unsigned sptr(const void* p) {
    return (unsigned)__cvta_generic_to_shared(p);
}

__device__ __forceinline__ void ldsm4(unsigned& r0, unsigned& r1,
                                      unsigned& r2, unsigned& r3, unsigned a) {
    asm volatile("ldmatrix.sync.aligned.m8n8.x4.shared.b16 {%0,%1,%2,%3}, [%4];"
                 : "=r"(r0), "=r"(r1), "=r"(r2), "=r"(r3) : "r"(a));
}

__device__ __forceinline__ void ldsm4t(unsigned& r0, unsigned& r1,
                                       unsigned& r2, unsigned& r3, unsigned a) {
    asm volatile("ldmatrix.sync.aligned.m8n8.x4.trans.shared.b16 {%0,%1,%2,%3}, [%4];"
                 : "=r"(r0), "=r"(r1), "=r"(r2), "=r"(r3) : "r"(a));
}

__device__ __forceinline__ void mma16816(float* c, const unsigned* a,
                                         unsigned b0, unsigned b1) {
    asm volatile(
        "mma.sync.aligned.m16n8k16.row.col.f32.f16.f16.f32 "
        "{%0,%1,%2,%3},{%4,%5,%6,%7},{%8,%9},{%0,%1,%2,%3};"
        : "+f"(c[0]), "+f"(c[1]), "+f"(c[2]), "+f"(c[3])
        : "r"(a[0]), "r"(a[1]), "r"(a[2]), "r"(a[3]), "r"(b0), "r"(b1));
}

__device__ __forceinline__ unsigned pack2(float x, float y) {
    __half2 h = __floats2half2_rn(x, y);
    return *(unsigned*)&h;
}

// exact *0.125 on packed fp16x2 (exponent shift)
__device__ __forceinline__ unsigned scale8(unsigned v) {
    __half2 t = *(__half2*)&v;
    t = __hmul2(t, __floats2half2_rn(0.125f, 0.125f));
    return *(unsigned*)&t;
}

// cp.async
__device__ __forceinline__ void cp16(unsigned saddr, const void* g) {
    asm volatile("cp.async.cg.shared.global [%0], [%1], 16;\n"
                 :: "r"(saddr), "l"(g));
}
template<int N> __device__ __forceinline__ void cp_wait() {
    asm volatile("cp.async.wait_group %0;\n" :: "n"(N) : "memory");
}
__device__ __forceinline__ void cp_commit() {
    asm volatile("cp.async.commit_group;\n" ::: "memory");
}

// ---------------------------------------------------------------------------
// Fused fp32 -> fp16 rounding of x, w_qkv, w_out in one launch.
// All sizes are multiples of 4.
// ---------------------------------------------------------------------------
__global__ __launch_bounds__(256) void round3_f16(
    const float* __restrict__ x,  __half* __restrict__ xo,  int nx,
    const float* __restrict__ w1, __half* __restrict__ w1o, int n1,
    const float* __restrict__ w2, __half* __restrict__ w2o, int n2)
{
    int base = (blockIdx.x * blockDim.x + threadIdx.x) * 4;
    const float* src;
    __half* dst;
    if (base < nx) {
        src = x + base; dst = xo + base;
    } else if (base < nx + n1) {
        src = w1 + (base - nx); dst = w1o + (base - nx);
    } else if (base < nx + n1 + n2) {
        src = w2 + (base - nx - n1); dst = w2o + (base - nx - n1);
    } else return;
    float4 v = *(const float4*)src;
    *(unsigned*)dst       = pack2(v.x, v.y);
    *(unsigned*)(dst + 2) = pack2(v.z, v.w);
}

// ---------------------------------------------------------------------------
// HMMA GEMM (NT), fp16: C = A*W^T (+bias).  (R12/R14 configuration — best.)
// CTA tile 128x128, 4 warps (128 threads) in 2x2, warp tile 64x64, BK=32.
// 4-stage cp.async ring, ONE __syncthreads per K-slab. 2 CTAs/SM.
// ---------------------------------------------------------------------------
#define PADK 40
#define STAGE_B 20480u    // 10240 (A 128x40) + 10240 (W 128x40)

__global__ __launch_bounds__(128) void gemm_f16(
    const __half* __restrict__ A, const __half* __restrict__ W,
    float* __restrict__ Cf, __half* __restrict__ Ch,
    const float* __restrict__ bias,
    int M, int N, int K)
{
    extern __shared__ __align__(16) __half sm[];

    const int tid  = threadIdx.x;
    const int lane = tid & 31;
    const int warp = tid >> 5;
    const int wm = (warp >> 1) * 64;
    const int wn = (warp & 1) * 64;
    const int brow = blockIdx.y * 128;
    const int bcol = blockIdx.x * 128;
    const int nch  = K >> 5;   // 32

    const int tt  = lane >> 3;
    const int lr8 = lane & 7;
    const unsigned smb = sptr(sm);

    float acc[4][8][4];
#pragma unroll
    for (int mt = 0; mt < 4; mt++)
#pragma unroll
        for (int nt = 0; nt < 8; nt++)
#pragma unroll
            for (int i = 0; i < 4; i++) acc[mt][nt][i] = 0.0f;

    auto load_stage = [&](int c, int s) {
        const int k0 = c << 5;
        const unsigned sb = smb + (unsigned)s * STAGE_B;
#pragma unroll
        for (int i = 0; i < 4; i++) {          // A: 128 rows x 32 cols
            int idx = i * 128 + tid;
            int row = idx >> 2;
            int cc  = (idx & 3) * 8;
            cp16(sb + (unsigned)(row * PADK + cc) * 2,
                 A + (size_t)(brow + row) * K + k0 + cc);
        }
#pragma unroll
        for (int i = 0; i < 4; i++) {          // W: 128 rows x 32 cols
            int idx = i * 128 + tid;
            int row = idx >> 2;
            int cc  = (idx & 3) * 8;
            cp16(sb + 10240u + (unsigned)(row * PADK + cc) * 2,
                 W + (size_t)(bcol + row) * K + k0 + cc);
        }
        cp_commit();
    };

    load_stage(0, 0);
    load_stage(1, 1);
    load_stage(2, 2);

    for (int c = 0; c < nch; c++) {
        int rem = nch - 1 - c;
        if (rem >= 2)      cp_wait<2>();
        else if (rem == 1) cp_wait<1>();
        else               cp_wait<0>();
        __syncthreads();

        if (c + 3 < nch) load_stage(c + 3, (c + 3) & 3);

        const unsigned sb  = smb + (unsigned)(c & 3) * STAGE_B;
        const unsigned sbW = sb + 10240u;

#pragma unroll
        for (int ks = 0; ks < 32; ks += 16) {
            unsigned bw[8][2];
#pragma unroll
            for (int i = 0; i < 4; i++) {
                int nrow = wn + (2 * i + (tt >> 1)) * 8 + lr8;
                int ncol = ks + (tt & 1) * 8;
                ldsm4(bw[2 * i][0], bw[2 * i][1], bw[2 * i + 1][0], bw[2 * i + 1][1],
                      sbW + (unsigned)(nrow * PADK + ncol) * 2);
            }
#pragma unroll
            for (int mt = 0; mt < 4; mt++) {
                unsigned ah[4];
                int arow = wm + mt * 16 + (tt & 1) * 8 + lr8;
                int acol = ks + (tt >> 1) * 8;
                ldsm4(ah[0], ah[1], ah[2], ah[3],
                      sb + (unsigned)(arow * PADK + acol) * 2);
#pragma unroll
                for (int nt = 0; nt < 8; nt++)
                    mma16816(acc[mt][nt], ah, bw[nt][0], bw[nt][1]);
            }
        }
    }

    const int r  = lane >> 2;
    const int cq = lane & 3;
#pragma unroll
    for (int mt = 0; mt < 4; mt++) {
#pragma unroll
        for (int nt = 0; nt < 8; nt++) {
            int row0 = brow + wm + mt * 16 + r;
            int col0 = bcol + wn + nt * 8 + cq * 2;
            float b0 = 0.f, b1 = 0.f;
            if (bias != nullptr) { b0 = bias[col0]; b1 = bias[col0 + 1]; }
            float v0 = acc[mt][nt][0] + b0, v1 = acc[mt][nt][1] + b1;
            float v2 = acc[mt][nt][2] + b0, v3 = acc[mt][nt][3] + b1;
            if (Cf != nullptr) {
                *(float2*)(Cf + (size_t)row0 * N + col0)       = make_float2(v0, v1);
                *(float2*)(Cf + (size_t)(row0 + 8) * N + col0) = make_float2(v2, v3);
            }
            if (Ch != nullptr) {
                *(unsigned*)(Ch + (size_t)row0 * N + col0)       = pack2(v0, v1);
                *(unsigned*)(Ch + (size_t)(row0 + 8) * N + col0) = pack2(v2, v3);
            }
        }
    }
}

// ---------------------------------------------------------------------------
// Causal flash attention, fp16. Grid (16, 64). Br=128, Bc=64; 128 threads,
// 4 warps; warp w owns rows w*32..w*32+31 (two 16-row m-tiles).
// 4-stage cp.async ring; tiles processed in PAIRS (nkt = 2qt+2 is even):
// one cp_wait + __syncthreads per 2 tiles. At a pair boundary kt, tile kt+2
// targets stage (kt-2)&3 (readers done at kt-2) and kt+3 targets (kt-1)&3
// (readers done at kt-1, enforced by this boundary's sync).
// ---------------------------------------------------------------------------
#define SKP 72                 // smem row stride in fp16 (conflict-free LDSM)
#define KV_HALF 9216u          // 64*72*2 bytes (one K or V buffer)
#define KV_STAGE 18432u        // K + V per stage

__global__ __launch_bounds__(128) void flash_attn_f16(
    const __half* __restrict__ qkv, __half* __restrict__ outp)
{
    extern __shared__ __align__(16) __half smA[];   // 4 stages x (K|V)

    const int tid  = threadIdx.x;
    const int lane = tid & 31;
    const int w    = tid >> 5;
    const int qt   = (gridDim.x - 1) - blockIdx.x;   // heavy tiles first
    const int bh   = blockIdx.y;
    const int b    = bh >> 4;
    const int h    = bh & 15;

    const int tt  = lane >> 3;
    const int lr8 = lane & 7;
    const int r   = lane >> 2;
    const int cq  = lane & 3;
    const unsigned smb = sptr(smA);

    // ---- stage Q (two 64-row halves through stage-0 K buffer) ----
    unsigned qa[2][4][4];
#pragma unroll
    for (int half = 0; half < 2; half++) {
        __syncthreads();
#pragma unroll
        for (int i = 0; i < 4; i++) {
            int idx = tid + i * 128;
            int row = idx >> 3;
            int c8  = (idx & 7) * 8;
            size_t g = (size_t)(b * TT + qt * 128 + half * 64 + row) * C3 + h * DD + c8;
            *(uint4*)(smA + row * SKP + c8) = *(const uint4*)(qkv + g);
        }
        __syncthreads();
        if ((w >> 1) == half) {
            int wq = (w & 1) * 32;
#pragma unroll
            for (int mq = 0; mq < 2; mq++) {
#pragma unroll
                for (int kc = 0; kc < 4; kc++) {
                    int qrow = wq + mq * 16 + (tt & 1) * 8 + lr8;
                    int qcol = kc * 16 + (tt >> 1) * 8;
                    ldsm4(qa[mq][kc][0], qa[mq][kc][1], qa[mq][kc][2], qa[mq][kc][3],
                          smb + (unsigned)(qrow * SKP + qcol) * 2);
#pragma unroll
                    for (int j = 0; j < 4; j++)
                        qa[mq][kc][j] = scale8(qa[mq][kc][j]);   // fold 1/sqrt(D)
                }
            }
        }
    }
    __syncthreads();   // Q frags extracted before K overwrites stage 0

    float o[2][8][4];
#pragma unroll
    for (int mq = 0; mq < 2; mq++)
#pragma unroll
        for (int nt = 0; nt < 8; nt++)
#pragma unroll
            for (int j = 0; j < 4; j++) o[mq][nt][j] = 0.0f;
    float mx[2][2] = {{-1e30f, -1e30f}, {-1e30f, -1e30f}};
    float li[2][2] = {{0.f, 0.f}, {0.f, 0.f}};

    const int nkt = 2 * qt + 2;   // always even

    // cp.async K/V tile loader: tile kt -> stage s (one commit group per tile)
    auto load_tile = [&](int kt, int s) {
        const unsigned sb = smb + (unsigned)s * KV_STAGE;
        size_t base = (size_t)(b * TT + kt * 64) * C3 + h * DD;
#pragma unroll
        for (int i = 0; i < 4; i++) {
            int idx = tid + i * 128;
            int row = idx >> 3;
            int c8  = (idx & 7) * 8;
            unsigned d = sb + (unsigned)(row * SKP + c8) * 2;
            size_t g = base + (size_t)row * C3 + c8;
            cp16(d,           qkv + g + CC);       // K
            cp16(d + KV_HALF, qkv + g + 2 * CC);   // V
        }
        cp_commit();
    };

    load_tile(0, 0);
    load_tile(1, 1);

    for (int kt = 0; kt < nkt; kt += 2) {
        cp_wait<0>();          // drain tiles kt, kt+1 (issued one boundary ago)
        __syncthreads();       // all warps done reading stages (kt-2)&3,(kt-1)&3

        if (kt + 2 < nkt) load_tile(kt + 2, (kt + 2) & 3);
        if (kt + 3 < nkt) load_tile(kt + 3, (kt + 3) & 3);

#pragma unroll
        for (int t = 0; t < 2; t++) {
            const int ktt = kt + t;
            const unsigned sbK = smb + (unsigned)(ktt & 3) * KV_STAGE;
            const unsigned sbV = sbK + KV_HALF;

            if (ktt * 64 <= qt * 128 + w * 32 + 31) {
                // ---- scores: S = Q·K^T (both m-tiles share K frags) ----
                float s[2][8][4];
#pragma unroll
                for (int mq = 0; mq < 2; mq++)
#pragma unroll
                    for (int nt = 0; nt < 8; nt++)
#pragma unroll
                        for (int j = 0; j < 4; j++) s[mq][nt][j] = 0.0f;

#pragma unroll
                for (int kc = 0; kc < 4; kc++) {
                    unsigned kb[8][2];
#pragma unroll
                    for (int i = 0; i < 4; i++) {
                        int nrow = (2 * i + (tt >> 1)) * 8 + lr8;
                        int ncol = kc * 16 + (tt & 1) * 8;
                        ldsm4(kb[2 * i][0], kb[2 * i][1], kb[2 * i + 1][0], kb[2 * i + 1][1],
                              sbK + (unsigned)(nrow * SKP + ncol) * 2);
                    }
#pragma unroll
                    for (int mq = 0; mq < 2; mq++)
#pragma unroll
                        for (int nt = 0; nt < 8; nt++)
                            mma16816(s[mq][nt], qa[mq][kc], kb[nt][0], kb[nt][1]);
                }

                // ---- causal mask (diagonal-crossing tiles only) ----
                if (ktt >= 2 * qt) {
                    int colb = ktt * 64 + cq * 2;
#pragma unroll
                    for (int mq = 0; mq < 2; mq++) {
                        int rowr  = qt * 128 + w * 32 + mq * 16 + r;
                        int rowr8 = rowr + 8;
#pragma unroll
                        for (int nt = 0; nt < 8; nt++) {
                            int c0 = colb + nt * 8;
                            if (c0 > rowr)      s[mq][nt][0] = -1e30f;
                            if (c0 + 1 > rowr)  s[mq][nt][1] = -1e30f;
                            if (c0 > rowr8)     s[mq][nt][2] = -1e30f;
                            if (c0 + 1 > rowr8) s[mq][nt][3] = -1e30f;
                        }
                    }
                }

                // ---- online softmax per m-tile ----
#pragma unroll
                for (int mq = 0; mq < 2; mq++) {
                    float mr = -1e30f, mr8 = -1e30f;
#pragma unroll
                    for (int nt = 0; nt < 8; nt++) {
                        mr  = fmaxf(mr,  fmaxf(s[mq][nt][0], s[mq][nt][1]));
                        mr8 = fmaxf(mr8, fmaxf(s[mq][nt][2], s[mq][nt][3]));
                    }
                    mr  = fmaxf(mr,  __shfl_xor_sync(0xffffffffu, mr, 1));
                    mr  = fmaxf(mr,  __shfl_xor_sync(0xffffffffu, mr, 2));
                    mr8 = fmaxf(mr8, __shfl_xor_sync(0xffffffffu, mr8, 1));
                    mr8 = fmaxf(mr8, __shfl_xor_sync(0xffffffffu, mr8, 2));

                    float mn  = fmaxf(mx[mq][0], mr);
                    float mn8 = fmaxf(mx[mq][1], mr8);
                    float ar  = __expf(mx[mq][0] - mn);
                    float ar8 = __expf(mx[mq][1] - mn8);
                    mx[mq][0] = mn; mx[mq][1] = mn8;

                    float lsr = 0.f, lsr8 = 0.f;
#pragma unroll
                    for (int nt = 0; nt < 8; nt++) {
                        float p0 = __expf(s[mq][nt][0] - mn);
                        float p1 = __expf(s[mq][nt][1] - mn);
                        float p2 = __expf(s[mq][nt][2] - mn8);
                        float p3 = __expf(s[mq][nt][3] - mn8);
                        lsr += p0 + p1; lsr8 += p2 + p3;
                        s[mq][nt][0] = p0; s[mq][nt][1] = p1;
                        s[mq][nt][2] = p2; s[mq][nt][3] = p3;
                        o[mq][nt][0] *= ar;  o[mq][nt][1] *= ar;
                        o[mq][nt][2] *= ar8; o[mq][nt][3] *= ar8;
                    }
                    li[mq][0] = li[mq][0] * ar  + lsr;
                    li[mq][1] = li[mq][1] * ar8 + lsr8;
                }

                // ---- PV: O += P·V (both m-tiles share V frags) ----
#pragma unroll
                for (int kc = 0; kc < 4; kc++) {
                    unsigned pa[2][4];
#pragma unroll
                    for (int mq = 0; mq < 2; mq++) {
                        pa[mq][0] = pack2(s[mq][2 * kc][0],     s[mq][2 * kc][1]);
                        pa[mq][1] = pack2(s[mq][2 * kc][2],     s[mq][2 * kc][3]);
                        pa[mq][2] = pack2(s[mq][2 * kc + 1][0], s[mq][2 * kc + 1][1]);
                        pa[mq][3] = pack2(s[mq][2 * kc + 1][2], s[mq][2 * kc + 1][3]);
                    }
                    unsigned vb[8][2];
#pragma unroll
                    for (int i = 0; i < 4; i++) {
                        int vrow = kc * 16 + (tt & 1) * 8 + lr8;
                        int vcol = (2 * i + (tt >> 1)) * 8;
                        ldsm4t(vb[2 * i][0], vb[2 * i][1], vb[2 * i + 1][0], vb[2 * i + 1][1],
                               sbV + (unsigned)(vrow * SKP + vcol) * 2);
                    }
#pragma unroll
                    for (int mq = 0; mq < 2; mq++)
#pragma unroll
                        for (int nt = 0; nt < 8; nt++)
                            mma16816(o[mq][nt], pa[mq], vb[nt][0], vb[nt][1]);
                }
            }
        }
    }

    // ---- finalize ----
#pragma unroll
    for (int mq = 0; mq < 2; mq++) {
        float l0 = li[mq][0], l8 = li[mq][1];
        l0 += __shfl_xor_sync(0xffffffffu, l0, 1);
        l0 += __shfl_xor_sync(0xffffffffu, l0, 2);
        l8 += __shfl_xor_sync(0xffffffffu, l8, 1);
        l8 += __shfl_xor_sync(0xffffffffu, l8, 2);
        float inv  = 1.0f / l0;
        float inv8 = 1.0f / l8;
        int rowr  = qt * 128 + w * 32 + mq * 16 + r;
        int rowr8 = rowr + 8;
#pragma unroll
        for (int nt = 0; nt < 8; nt++) {
            size_t a0 = (size_t)(b * TT + rowr)  * CC + h * DD + nt * 8 + cq * 2;
            size_t a1 = (size_t)(b * TT + rowr8) * CC + h * DD + nt * 8 + cq * 2;
            *(unsigned*)(outp + a0) = pack2(o[mq][nt][0] * inv,  o[mq][nt][1] * inv);
            *(unsigned*)(outp + a1) = pack2(o[mq][nt][2] * inv8, o[mq][nt][3] * inv8);
        }
    }
}

// ---------------------------------------------------------------------------
extern "C" void kernel_launch(void* const* d_in, const int* in_sizes, int n_in,
                              void* d_out, int out_size)
{
    const float* x     = (const float*)d_in[0];
    const float* w_qkv = (const float*)d_in[1];
    const float* w_out = (const float*)d_in[2];
    const float* b_out = (const float*)d_in[3];
    float* out = (float*)d_out;

    __half *x16, *wq16, *wo16, *qkv16, *at16;
    cudaGetSymbolAddress((void**)&x16,   g_x16);
    cudaGetSymbolAddress((void**)&wq16,  g_wq16);
    cudaGetSymbolAddress((void**)&wo16,  g_wo16);
    cudaGetSymbolAddress((void**)&qkv16, g_qkv16);
    cudaGetSymbolAddress((void**)&at16,  g_at16);

    const int dsmemG = 4 * (int)STAGE_B;   // 80KB GEMM ring
    const int dsmemA = 4 * (int)KV_STAGE;  // 72KB attention ring
    cudaFuncSetAttribute(gemm_f16, cudaFuncAttributeMaxDynamicSharedMemorySize, dsmemG);
    cudaFuncSetAttribute(flash_attn_f16, cudaFuncAttributeMaxDynamicSharedMemorySize, dsmemA);

    // 0) round inputs to fp16 (single fused launch)
    {
        int nx = MTOT * CC;
        int n1 = C3 * CC;
        int n2 = CC * CC;
        int total4 = (nx + n1 + n2) / 4;
        round3_f16<<<(total4 + 255) / 256, 256>>>(x, x16, nx, w_qkv, wq16, n1,
                                                  w_out, wo16, n2);
    }

    // 1) QKV projection -> fp16
    {
        dim3 grid(C3 / 128, MTOT / 128);
        gemm_f16<<<grid, 128, dsmemG>>>(x16, wq16, nullptr, qkv16, nullptr, MTOT, C3, CC);
    }

    // 2) causal flash attention -> fp16
    {
        dim3 grid(TT / 128, BB * HH);
        flash_attn_f16<<<grid, 128, dsmemA>>>(qkv16, at16);
    }

    // 3) out projection + bias -> fp32 output
    {
        dim3 grid(CC / 128, MTOT / 128);
        gemm_f16<<<grid, 128, dsmemG>>>(at16, wo16, out, nullptr, b_out, MTOT, CC, CC);
    }
}